// round 12
// baseline (speedup 1.0000x reference)
#include <cuda_runtime.h>
#include <cuda_pipeline.h>

// Shapes: probs (2,2,32,512,512) fp32, gt_mask (2,32,512,512) int32.
// Output: scalar fp32 = mean over all of (probs - onehot(target))^2,
// target = (gt == 1) since ignore_index=2 -> 0 and clamp [0,1].
//
// FINAL (resubmit after R11 container infra failure): cp.async (LDGSTS)
// 3-stage per-thread pipeline. Best measured: kernel 32.5us, DRAM 80% =
// 6331 GB/s == the sm_103a LTS chip cap (~6300 B/cyc, path-independent).
// 201.3 MB / 6.33 TB/s floor = 31.8us; this runs at ~98% of it. Deeper
// stages (R10) and register unrolling (R5/R8) both regressed.
// Tail: one packed 64-bit atomicAdd per block {count[52:], fixed-point
// sum x 2^20 [0:52)} -> bitwise-deterministic graph replays.

constexpr int DHW     = 32 * 512 * 512;    // 8388608 = 2^23
constexpr int VEC     = (2 * DHW) / 4;     // 4194304 int4/float4 groups
constexpr int DHW4    = DHW / 4;           // 2097152 = 2^21
constexpr int BLOCKS  = 1024;
constexpr int THREADS = 128;
constexpr int GSTRIDE = BLOCKS * THREADS;  // 131072 = 2^17
constexpr int TRIPS   = VEC / GSTRIDE;     // 32 (exact)
constexpr int STAGES  = 3;
static_assert(TRIPS * GSTRIDE == VEC, "exact tiling");

constexpr unsigned long long COUNT_ONE = 1ULL << 52;
constexpr unsigned long long SUM_MASK  = COUNT_ONE - 1ULL;

__device__ unsigned long long g_accum;  // zero-init at load; reset by last block

__device__ __forceinline__ float warp_sum(float v) {
    #pragma unroll
    for (int o = 16; o > 0; o >>= 1)
        v += __shfl_xor_sync(0xFFFFFFFFu, v, o);
    return v;
}

__global__ __launch_bounds__(THREADS) void mse_pipe_kernel(
    const float* __restrict__ probs, const int* __restrict__ gt,
    float* __restrict__ out)
{
    const float4* __restrict__ p4 = reinterpret_cast<const float4*>(probs);
    const int4*   __restrict__ g4 = reinterpret_cast<const int4*>(gt);

    __shared__ int4   s_g [STAGES][THREADS];
    __shared__ float4 s_p0[STAGES][THREADS];
    __shared__ float4 s_p1[STAGES][THREADS];

    const int tx  = threadIdx.x;
    const int tid = blockIdx.x * THREADS + tx;

    // Issue one trip's 3 async copies into the given stage.
    auto issue = [&](int trip, int st) {
        int idx = tid + trip * GSTRIDE;
        int b = idx >> 21;             // DHW4 = 2^21
        int r = idx & (DHW4 - 1);
        __pipeline_memcpy_async(&s_g [st][tx], &g4[idx], 16);
        __pipeline_memcpy_async(&s_p0[st][tx], &p4[(size_t)(2 * b    ) * DHW4 + r], 16);
        __pipeline_memcpy_async(&s_p1[st][tx], &p4[(size_t)(2 * b + 1) * DHW4 + r], 16);
    };

    // Prologue: fill all stages.
    #pragma unroll
    for (int s = 0; s < STAGES; s++) {
        issue(s, s);
        __pipeline_commit();
    }

    float acc = 0.0f;
    for (int t = 0; t < TRIPS; t++) {
        __pipeline_wait_prior(STAGES - 1);   // group t (oldest) complete
        int st = t % STAGES;

        int4   g  = s_g [st][tx];
        float4 p0 = s_p0[st][tx];
        float4 p1 = s_p1[st][tx];

        // Refill this stage (empty commit on the tail keeps group math uniform).
        if (t + STAGES < TRIPS) issue(t + STAGES, st);
        __pipeline_commit();

        // onehot: oh0 = (gt != 1), oh1 = (gt == 1)
        float d;
        d = p0.x - (float)(g.x != 1); acc = fmaf(d, d, acc);
        d = p1.x - (float)(g.x == 1); acc = fmaf(d, d, acc);
        d = p0.y - (float)(g.y != 1); acc = fmaf(d, d, acc);
        d = p1.y - (float)(g.y == 1); acc = fmaf(d, d, acc);
        d = p0.z - (float)(g.z != 1); acc = fmaf(d, d, acc);
        d = p1.z - (float)(g.z == 1); acc = fmaf(d, d, acc);
        d = p0.w - (float)(g.w != 1); acc = fmaf(d, d, acc);
        d = p1.w - (float)(g.w == 1); acc = fmaf(d, d, acc);
    }

    // Block reduction: warp shuffles -> smem -> thread 0
    __shared__ float smem[THREADS / 32];
    acc = warp_sum(acc);
    int lane = tx & 31;
    int wid  = tx >> 5;
    if (lane == 0) smem[wid] = acc;
    __syncthreads();

    if (tx == 0) {
        float v = 0.0f;
        #pragma unroll
        for (int i = 0; i < THREADS / 32; i++) v += smem[i];

        // Fixed-point encode (round to nearest) + arrival count, one atom.
        unsigned long long mine =
            COUNT_ONE | (unsigned long long)(v * 1048576.0f + 0.5f);
        unsigned long long prev = atomicAdd(&g_accum, mine);
        unsigned long long now  = prev + mine;

        if ((now >> 52) == (unsigned long long)gridDim.x) {
            float total = (float)((double)(now & SUM_MASK) * 0x1p-45);
            out[0] = total;                 // 2^-20 (scale) * 2^-25 (1/N)
            g_accum = 0ULL;                 // restore invariant for next replay
        }
    }
}

extern "C" void kernel_launch(void* const* d_in, const int* in_sizes, int n_in,
                              void* d_out, int out_size)
{
    const float* probs = (const float*)d_in[0];
    const int*   gt    = (const int*)d_in[1];
    float*       out   = (float*)d_out;

    mse_pipe_kernel<<<BLOCKS, THREADS>>>(probs, gt, out);
}

// round 13
// speedup vs baseline: 1.0521x; 1.0521x over previous
#include <cuda_runtime.h>

// Shapes: probs (2,2,32,512,512) fp32, gt_mask (2,32,512,512) int32.
// Output: scalar fp32 = mean over all of (probs - onehot(target))^2,
// target = (gt == 1) since ignore_index=2 -> 0 and clamp [0,1].
//
// FINAL: plain streaming-load grid-stride loop, full-residency grid
// (1184 = 148 SMs x 8 CTAs). The chip is pinned at the sm_103a LTS
// throughput cap (~6300 B/cyc, path-independent): plain LDG, tuned
// LDG, and cp.async pipelines all measure 6.0-6.33 TB/s; unrolling
// (R5/R8) and deeper pipelines (R10) regressed. This config has the
// best measured total (33.57us) with the least non-memory overhead
// (26 regs, no smem staging).
// Tail: one packed 64-bit atomicAdd per block {count[52:], fixed-point
// sum x 2^20 [0:52)}; integer adds -> bitwise-deterministic replays.

constexpr int DHW      = 32 * 512 * 512;   // 8388608 = 2^23
constexpr int NGT      = 2 * DHW;          // 16777216
constexpr int VEC      = NGT / 4;          // 4194304 int4/float4 groups
constexpr int DHW4     = DHW / 4;          // 2097152 = 2^21
constexpr int BLOCKS   = 1184;             // 148 SMs * 8 CTAs
constexpr int THREADS  = 256;

// Fixed-point: block partial < 2^15 -> *2^20 < 2^35; 1184 blocks -> < 2^46.
// Count lives in bits [52:]; no overlap with the sum field.
constexpr unsigned long long COUNT_ONE = 1ULL << 52;
constexpr unsigned long long SUM_MASK  = COUNT_ONE - 1ULL;

__device__ unsigned long long g_accum;  // zero-init at load; reset by last block

__device__ __forceinline__ float warp_sum(float v) {
    #pragma unroll
    for (int o = 16; o > 0; o >>= 1)
        v += __shfl_xor_sync(0xFFFFFFFFu, v, o);
    return v;
}

__global__ __launch_bounds__(THREADS) void mse_fused_kernel(
    const float* __restrict__ probs, const int* __restrict__ gt,
    float* __restrict__ out)
{
    const float4* __restrict__ p4 = reinterpret_cast<const float4*>(probs);
    const int4*   __restrict__ g4 = reinterpret_cast<const int4*>(gt);

    float acc = 0.0f;
    const int stride = gridDim.x * blockDim.x;
    for (int idx = blockIdx.x * blockDim.x + threadIdx.x; idx < VEC; idx += stride) {
        int4 g = __ldcs(&g4[idx]);
        int b = idx >> 21;            // DHW4 = 2^21
        int r = idx & (DHW4 - 1);
        // probs layout (B, C, D, H, W): channel stride = DHW
        float4 p0 = __ldcs(&p4[(size_t)(2 * b    ) * DHW4 + r]);  // c = 0
        float4 p1 = __ldcs(&p4[(size_t)(2 * b + 1) * DHW4 + r]);  // c = 1

        // onehot: oh0 = (gt != 1), oh1 = (gt == 1)
        float d;
        d = p0.x - (float)(g.x != 1); acc = fmaf(d, d, acc);
        d = p1.x - (float)(g.x == 1); acc = fmaf(d, d, acc);
        d = p0.y - (float)(g.y != 1); acc = fmaf(d, d, acc);
        d = p1.y - (float)(g.y == 1); acc = fmaf(d, d, acc);
        d = p0.z - (float)(g.z != 1); acc = fmaf(d, d, acc);
        d = p1.z - (float)(g.z == 1); acc = fmaf(d, d, acc);
        d = p0.w - (float)(g.w != 1); acc = fmaf(d, d, acc);
        d = p1.w - (float)(g.w == 1); acc = fmaf(d, d, acc);
    }

    // Block reduction: warp shuffles -> smem -> thread 0
    __shared__ float smem[THREADS / 32];
    acc = warp_sum(acc);
    int lane = threadIdx.x & 31;
    int wid  = threadIdx.x >> 5;
    if (lane == 0) smem[wid] = acc;
    __syncthreads();

    if (threadIdx.x == 0) {
        float v = 0.0f;
        #pragma unroll
        for (int i = 0; i < THREADS / 32; i++) v += smem[i];

        // Fixed-point encode (round to nearest) + arrival count, one atom.
        unsigned long long mine =
            COUNT_ONE | (unsigned long long)(v * 1048576.0f + 0.5f);
        unsigned long long prev = atomicAdd(&g_accum, mine);
        unsigned long long now  = prev + mine;

        if ((now >> 52) == (unsigned long long)gridDim.x) {
            // Last block: low bits hold the exact fixed-point total.
            float total = (float)((double)(now & SUM_MASK) * 0x1p-45);
            out[0] = total;                 // 2^-20 (scale) * 2^-25 (1/N)
            g_accum = 0ULL;                 // restore invariant for next replay
        }
    }
}

extern "C" void kernel_launch(void* const* d_in, const int* in_sizes, int n_in,
                              void* d_out, int out_size)
{
    const float* probs = (const float*)d_in[0];
    const int*   gt    = (const int*)d_in[1];
    float*       out   = (float*)d_out;

    mse_fused_kernel<<<BLOCKS, THREADS>>>(probs, gt, out);
}